// round 5
// baseline (speedup 1.0000x reference)
#include <cuda_runtime.h>
#include <math.h>
#include <stdint.h>

// Problem constants
#define TSEQ 2048
#define NHEAD 16
#define HDIM 128
// mask: keep k < 204 or k >= 1229 ; evict = 1229 ; recent count rb = 819
// last_start = 1792 ; mean over k in [1230, 2048) -> 818 elements

// ---------------- scratch (static device globals; no allocation) -------------
__device__ float g_q[NHEAD * TSEQ * HDIM];   // [h][t][d], rope applied
__device__ float g_k[NHEAD * TSEQ * HDIM];
__device__ float g_v[NHEAD * TSEQ * HDIM];
__device__ float g_ctx[TSEQ * 2048];         // [t][h*128+d]
__device__ float g_ve[NHEAD * HDIM];         // v_e per head (already includes bern/rb)

// nan_to_num(nan=0, posinf=1e4, neginf=-1e4): replaces non-finite ONLY
__device__ __forceinline__ float nn_fix(float x) {
    if (isnan(x)) return 0.0f;
    if (isinf(x)) return x > 0.0f ? 10000.0f : -10000.0f;
    return x;
}

// ---------------- SGEMM: C[M,N] = A[M,K] * B[N,K]^T (NT), M=N=K=2048 ----------
// Pure fp32 FFMA (reference is full-precision fp32).
// mode 0/1/2 : A = Aext (nan_to_num'd), C -> g_q/g_k/g_v in [head][t][d]
// mode 3     : A = g_ctx, C -> Cext row-major with nan_to_num
__global__ void __launch_bounds__(256, 2)
sgemm_nt_kernel(const float* __restrict__ Aext, const float* __restrict__ B,
                float* __restrict__ Cext, int mode)
{
    __shared__ float As[16][132];
    __shared__ float Bs[16][132];

    const float* A = (mode == 3) ? (const float*)g_ctx : Aext;
    const bool fixA = (mode != 3);

    const int tid = threadIdx.x;
    const int bm = blockIdx.y;
    const int bn = blockIdx.x;
    const int tm0 = (tid >> 4) << 3;   // 0..120
    const int tn0 = (tid & 15) << 3;   // 0..120
    const int lr = tid >> 2;           // 0..63
    const int lc = (tid & 3) << 2;     // 0,4,8,12

    float acc[8][8];
#pragma unroll
    for (int i = 0; i < 8; ++i)
#pragma unroll
        for (int j = 0; j < 8; ++j) acc[i][j] = 0.0f;

    const float* Ab = A + (size_t)(bm * 128) * 2048;
    const float* Bb = B + (size_t)(bn * 128) * 2048;

    for (int k0 = 0; k0 < 2048; k0 += 16) {
#pragma unroll
        for (int it = 0; it < 2; ++it) {
            int r = lr + it * 64;
            float4 va = *(const float4*)(Ab + (size_t)r * 2048 + k0 + lc);
            if (fixA) {
                va.x = nn_fix(va.x); va.y = nn_fix(va.y);
                va.z = nn_fix(va.z); va.w = nn_fix(va.w);
            }
            As[lc + 0][r] = va.x; As[lc + 1][r] = va.y;
            As[lc + 2][r] = va.z; As[lc + 3][r] = va.w;
            float4 vb = *(const float4*)(Bb + (size_t)r * 2048 + k0 + lc);
            Bs[lc + 0][r] = vb.x; Bs[lc + 1][r] = vb.y;
            Bs[lc + 2][r] = vb.z; Bs[lc + 3][r] = vb.w;
        }
        __syncthreads();
#pragma unroll
        for (int kk = 0; kk < 16; ++kk) {
            float a[8], b[8];
            *(float4*)&a[0] = *(const float4*)&As[kk][tm0];
            *(float4*)&a[4] = *(const float4*)&As[kk][tm0 + 4];
            *(float4*)&b[0] = *(const float4*)&Bs[kk][tn0];
            *(float4*)&b[4] = *(const float4*)&Bs[kk][tn0 + 4];
#pragma unroll
            for (int i = 0; i < 8; ++i)
#pragma unroll
                for (int j = 0; j < 8; ++j)
                    acc[i][j] = fmaf(a[i], b[j], acc[i][j]);
        }
        __syncthreads();
    }

    if (mode == 3) {
#pragma unroll
        for (int i = 0; i < 8; ++i) {
            const size_t row = (size_t)(bm * 128 + tm0 + i);
#pragma unroll
            for (int j = 0; j < 8; ++j)
                Cext[row * 2048 + bn * 128 + tn0 + j] = nn_fix(acc[i][j]);
        }
    } else {
        float* Cg = (mode == 0) ? g_q : (mode == 1) ? g_k : g_v;
        float* base = Cg + (size_t)bn * (TSEQ * HDIM);
#pragma unroll
        for (int i = 0; i < 8; ++i) {
            const size_t row = (size_t)(bm * 128 + tm0 + i);
#pragma unroll
            for (int j = 0; j < 8; ++j)
                base[row * HDIM + tn0 + j] = acc[i][j];
        }
    }
}

// ---------------- RoPE in-place on g_q, g_k ----------------------------------
// inv_freq: correctly-rounded f32 pow (double pow -> f32), then f32 divide,
// matching 1.0f / powf(10000, x) with a correctly-rounded powf (glibc).
__global__ void rope_kernel()
{
    const int t = blockIdx.x;      // 0..2047
    const int i = threadIdx.x;     // 0..63 (pair index)
    const float pw = (float)pow(10000.0, (double)(2 * i) / 128.0);
    const float inv = 1.0f / pw;
    const float freq = (float)t * inv;   // f32 product, same as reference
    const float c = cosf(freq);
    const float s = sinf(freq);
#pragma unroll 4
    for (int h = 0; h < NHEAD; ++h) {
        float* q = g_q + ((size_t)(h * TSEQ + t)) * HDIM;
        float x1 = q[i], x2 = q[i + 64];
        q[i]      = __fadd_rn(__fmul_rn(x1, c), __fmul_rn(-x2, s));
        q[i + 64] = __fadd_rn(__fmul_rn(x2, c), __fmul_rn(x1, s));
        float* k = g_k + ((size_t)(h * TSEQ + t)) * HDIM;
        float y1 = k[i], y2 = k[i + 64];
        k[i]      = __fadd_rn(__fmul_rn(y1, c), __fmul_rn(-y2, s));
        k[i + 64] = __fadd_rn(__fmul_rn(y2, c), __fmul_rn(y1, s));
    }
}

// ---------------- threefry-2x32, PARTITIONABLE path (JAX >= 0.4.36 default) --
// Element h gets 64-bit counter (hi=0, lo=h); 32-bit output = x0_final ^ x1_final.
__device__ __forceinline__ unsigned rotl32(unsigned x, int d) {
    return (x << d) | (x >> (32 - d));
}

__device__ float jax_uniform42_partitionable(int h)
{
    const unsigned k0 = 0u, k1 = 42u;
    const unsigned k2 = k0 ^ k1 ^ 0x1BD11BDAu;
    const unsigned ks[3] = { k0, k1, k2 };
    unsigned x0 = 0u + k0;              // counter hi = 0
    unsigned x1 = (unsigned)h + k1;     // counter lo = h
    const int rotA[4] = { 13, 15, 26, 6 };
    const int rotB[4] = { 17, 29, 16, 24 };
#pragma unroll
    for (int i = 0; i < 5; ++i) {
        const int* R = (i & 1) ? rotB : rotA;
#pragma unroll
        for (int j = 0; j < 4; ++j) {
            x0 += x1;
            x1 = rotl32(x1, R[j]);
            x1 ^= x0;
        }
        x0 += ks[(i + 1) % 3];
        x1 += ks[(i + 2) % 3] + (unsigned)(i + 1);
    }
    const unsigned bits = x0 ^ x1;
    return __uint_as_float((bits >> 9) | 0x3f800000u) - 1.0f;
}

// ---------------- last-row stats: p, bern, v_e per head ----------------------
__global__ void __launch_bounds__(256) lastrow_kernel()
{
    const int h = blockIdx.x;
    const int tid = threadIdx.x;
    __shared__ float qv[128];
    __shared__ float s[2048];
    __shared__ float red[256];
    __shared__ float red2[256];
    __shared__ float sh_scale;

    if (tid < 128) qv[tid] = g_q[((size_t)h * TSEQ + 2047) * HDIM + tid];
    __syncthreads();

    for (int k = tid; k < 2048; k += 256) {
        const bool keep = (k < 204) || (k >= 1229);
        float val = -INFINITY;
        if (keep) {
            const float4* kr = (const float4*)(g_k + ((size_t)h * TSEQ + k) * HDIM);
            const float4* q4 = (const float4*)qv;
            float dot = 0.0f;
#pragma unroll
            for (int d4 = 0; d4 < 32; ++d4) {
                float4 a = q4[d4]; float4 b = kr[d4];
                dot = fmaf(a.x, b.x, dot); dot = fmaf(a.y, b.y, dot);
                dot = fmaf(a.z, b.z, dot); dot = fmaf(a.w, b.w, dot);
            }
            val = dot / 11.313708498984760f;  // sqrt(128), f32 divide like ref
        }
        s[k] = val;
    }
    __syncthreads();

    float lm = -INFINITY;
    for (int k = tid; k < 2048; k += 256) lm = fmaxf(lm, s[k]);
    red[tid] = lm;
    __syncthreads();
    for (int st = 128; st > 0; st >>= 1) {
        if (tid < st) red[tid] = fmaxf(red[tid], red[tid + st]);
        __syncthreads();
    }
    const float m = red[0];
    __syncthreads();

    float ls = 0.0f, lrS = 0.0f;
    for (int k = tid; k < 2048; k += 256) {
        if ((k < 204) || (k >= 1229)) {
            const float e = expf(s[k] - m);
            ls += e;
            if (k >= 1230) lrS += e;
        }
    }
    red[tid] = ls; red2[tid] = lrS;
    __syncthreads();
    for (int st = 128; st > 0; st >>= 1) {
        if (tid < st) { red[tid] += red[tid + st]; red2[tid] += red2[tid + st]; }
        __syncthreads();
    }
    if (tid == 0) {
        const float L = red[0], R = red2[0];
        const float Pev = expf(s[1229] - m) / L;
        const float mean = (R / L) / 818.0f + 1e-6f;
        float p = Pev / mean;
        if (isnan(p)) p = 0.0f;
        p = fminf(fmaxf(p, 0.0f), 1.0f);
        const float u = jax_uniform42_partitionable(h);
        sh_scale = (u < p) ? 1.0f : 0.0f;
    }
    __syncthreads();
    if (tid < 128)
        g_ve[h * HDIM + tid] =
            (g_v[((size_t)h * TSEQ + 1229) * HDIM + tid] * sh_scale) / 819.0f;
}

// ---------------- flash-style attention over kept K columns ------------------
// grid: (32 q-tiles of 64 rows, 16 heads), 256 threads.
#define ATTN_SMEM_FLOATS (64*129 + 64*129 + 64*132 + 64*66 + 256)
#define ATTN_SMEM_BYTES  (ATTN_SMEM_FLOATS * 4)

__global__ void __launch_bounds__(256) attn_kernel()
{
    extern __shared__ float sm[];
    float* Qs   = sm;
    float* Ks   = Qs + 64 * 129;
    float* Vs   = Ks + 64 * 129;
    float* S    = Vs + 64 * 132;
    float* m_s  = S + 64 * 66;
    float* l_s  = m_s + 64;
    float* lr_s = l_s + 64;
    float* fac_s = lr_s + 64;

    const int h   = blockIdx.y;
    const int qt  = blockIdx.x;
    const int tid = threadIdx.x;
    const int ty  = tid >> 4;
    const int tx  = tid & 15;
    const int r0  = ty << 2;   // 4 q-rows per thread
    const int cS0 = tx << 2;   // 4 score cols per thread
    const int cV0 = tx << 3;   // 8 out cols per thread

    const int ldr = tid >> 5;          // 0..7
    const int ldc = (tid & 31) << 2;   // 0..124

    const float* qbase = g_q + ((size_t)h * TSEQ + qt * 64) * HDIM;
#pragma unroll
    for (int it = 0; it < 8; ++it) {
        const int j = ldr + it * 8;
        float4 v = *(const float4*)(qbase + (size_t)j * HDIM + ldc);
        Qs[j * 129 + ldc + 0] = v.x; Qs[j * 129 + ldc + 1] = v.y;
        Qs[j * 129 + ldc + 2] = v.z; Qs[j * 129 + ldc + 3] = v.w;
    }
    if (tid < 64) { m_s[tid] = -INFINITY; l_s[tid] = 0.0f; lr_s[tid] = 0.0f; }

    float acc[4][8];
#pragma unroll
    for (int i = 0; i < 4; ++i)
#pragma unroll
        for (int j = 0; j < 8; ++j) acc[i][j] = 0.0f;

    __syncthreads();

    for (int tile = 0; tile < 17; ++tile) {
        const int kb   = (tile < 4) ? tile * 64 : 1229 + (tile - 4) * 64;
        const int kend = (tile < 4) ? 204 : 2048;

#pragma unroll
        for (int it = 0; it < 8; ++it) {
            const int j = ldr + it * 8;
            const int kc = kb + j;
            float4 kv = make_float4(0.f, 0.f, 0.f, 0.f);
            float4 vv = kv;
            if (kc < kend) {
                kv = *(const float4*)(g_k + ((size_t)h * TSEQ + kc) * HDIM + ldc);
                vv = *(const float4*)(g_v + ((size_t)h * TSEQ + kc) * HDIM + ldc);
            }
            Ks[j * 129 + ldc + 0] = kv.x; Ks[j * 129 + ldc + 1] = kv.y;
            Ks[j * 129 + ldc + 2] = kv.z; Ks[j * 129 + ldc + 3] = kv.w;
            *(float4*)&Vs[j * 132 + ldc] = vv;
        }
        __syncthreads();

        // ---- S = Q * K^T (fp32 register outer product) ----
        float sacc[4][4];
#pragma unroll
        for (int i = 0; i < 4; ++i)
#pragma unroll
            for (int j = 0; j < 4; ++j) sacc[i][j] = 0.0f;

        const float* q0 = Qs + (r0 + 0) * 129;
        const float* q1 = Qs + (r0 + 1) * 129;
        const float* q2 = Qs + (r0 + 2) * 129;
        const float* q3 = Qs + (r0 + 3) * 129;
        const float* kp0 = Ks + (cS0 + 0) * 129;
        const float* kp1 = Ks + (cS0 + 1) * 129;
        const float* kp2 = Ks + (cS0 + 2) * 129;
        const float* kp3 = Ks + (cS0 + 3) * 129;
#pragma unroll 8
        for (int kk = 0; kk < 128; ++kk) {
            const float a0 = q0[kk], a1 = q1[kk], a2 = q2[kk], a3 = q3[kk];
            const float b0 = kp0[kk], b1 = kp1[kk], b2 = kp2[kk], b3 = kp3[kk];
            sacc[0][0] = fmaf(a0, b0, sacc[0][0]); sacc[0][1] = fmaf(a0, b1, sacc[0][1]);
            sacc[0][2] = fmaf(a0, b2, sacc[0][2]); sacc[0][3] = fmaf(a0, b3, sacc[0][3]);
            sacc[1][0] = fmaf(a1, b0, sacc[1][0]); sacc[1][1] = fmaf(a1, b1, sacc[1][1]);
            sacc[1][2] = fmaf(a1, b2, sacc[1][2]); sacc[1][3] = fmaf(a1, b3, sacc[1][3]);
            sacc[2][0] = fmaf(a2, b0, sacc[2][0]); sacc[2][1] = fmaf(a2, b1, sacc[2][1]);
            sacc[2][2] = fmaf(a2, b2, sacc[2][2]); sacc[2][3] = fmaf(a2, b3, sacc[2][3]);
            sacc[3][0] = fmaf(a3, b0, sacc[3][0]); sacc[3][1] = fmaf(a3, b1, sacc[3][1]);
            sacc[3][2] = fmaf(a3, b2, sacc[3][2]); sacc[3][3] = fmaf(a3, b3, sacc[3][3]);
        }
#pragma unroll
        for (int i = 0; i < 4; ++i)
#pragma unroll
            for (int j = 0; j < 4; ++j) {
                const int kc = kb + cS0 + j;
                S[(r0 + i) * 66 + cS0 + j] =
                    (kc < kend) ? sacc[i][j] / 11.313708498984760f : -1e30f;
            }
        __syncthreads();

        // ---- per-row online softmax update ----
        if (tid < 64) {
            const int r = tid;
            float* Sr = S + r * 66;
            float tm = -1e30f;
#pragma unroll 8
            for (int j = 0; j < 64; ++j) tm = fmaxf(tm, Sr[j]);
            const float mo = m_s[r];
            const float mn = fmaxf(mo, tm);
            const float fac = expf(mo - mn);
            float sum = 0.0f, sumr = 0.0f;
#pragma unroll 4
            for (int j = 0; j < 64; ++j) {
                const float e = expf(Sr[j] - mn);
                Sr[j] = e;
                sum += e;
                if (kb + j >= 1230) sumr += e;
            }
            l_s[r]  = l_s[r]  * fac + sum;
            lr_s[r] = lr_s[r] * fac + sumr;
            m_s[r]  = mn;
            fac_s[r] = fac;
        }
        __syncthreads();

        // ---- rescale acc, then acc += P * V ----
        {
            const float f0 = fac_s[r0 + 0], f1 = fac_s[r0 + 1];
            const float f2 = fac_s[r0 + 2], f3 = fac_s[r0 + 3];
#pragma unroll
            for (int j = 0; j < 8; ++j) {
                acc[0][j] *= f0; acc[1][j] *= f1; acc[2][j] *= f2; acc[3][j] *= f3;
            }
        }
#pragma unroll 2
        for (int jp = 0; jp < 64; ++jp) {
            const float p0 = S[(r0 + 0) * 66 + jp];
            const float p1 = S[(r0 + 1) * 66 + jp];
            const float p2 = S[(r0 + 2) * 66 + jp];
            const float p3 = S[(r0 + 3) * 66 + jp];
            float vv[8];
            *(float4*)&vv[0] = *(const float4*)&Vs[jp * 132 + cV0];
            *(float4*)&vv[4] = *(const float4*)&Vs[jp * 132 + cV0 + 4];
#pragma unroll
            for (int j = 0; j < 8; ++j) {
                acc[0][j] = fmaf(p0, vv[j], acc[0][j]);
                acc[1][j] = fmaf(p1, vv[j], acc[1][j]);
                acc[2][j] = fmaf(p2, vv[j], acc[2][j]);
                acc[3][j] = fmaf(p3, vv[j], acc[3][j]);
            }
        }
        __syncthreads();
    }

    // ---- epilogue: normalize, add v_e correction for q >= 1792 ----
    const int qg0 = qt * 64;
#pragma unroll
    for (int i = 0; i < 4; ++i) {
        const int r = r0 + i;
        const int qrow = qg0 + r;
        const float linv = 1.0f / l_s[r];
        const float corr = (qrow >= 1792) ? lr_s[r] * linv : 0.0f;
#pragma unroll
        for (int j = 0; j < 8; ++j) {
            const int dcol = cV0 + j;
            const float o = acc[i][j] * linv + corr * g_ve[h * HDIM + dcol];
            g_ctx[(size_t)qrow * 2048 + h * HDIM + dcol] = o;
        }
    }
}

// ---------------- launch ------------------------------------------------------
extern "C" void kernel_launch(void* const* d_in, const int* in_sizes, int n_in,
                              void* d_out, int out_size)
{
    (void)in_sizes; (void)n_in; (void)out_size;
    const float* hs = (const float*)d_in[0];
    const float* Wq = (const float*)d_in[1];
    const float* Wk = (const float*)d_in[2];
    const float* Wv = (const float*)d_in[3];
    const float* Wo = (const float*)d_in[4];
    float* out = (float*)d_out;

    dim3 ggrid(16, 16);
    sgemm_nt_kernel<<<ggrid, 256>>>(hs, Wq, nullptr, 0);
    sgemm_nt_kernel<<<ggrid, 256>>>(hs, Wk, nullptr, 1);
    sgemm_nt_kernel<<<ggrid, 256>>>(hs, Wv, nullptr, 2);
    rope_kernel<<<2048, 64>>>();
    lastrow_kernel<<<16, 256>>>();
    cudaFuncSetAttribute(attn_kernel,
                         cudaFuncAttributeMaxDynamicSharedMemorySize,
                         ATTN_SMEM_BYTES);
    attn_kernel<<<dim3(32, 16), 256, ATTN_SMEM_BYTES>>>();
    sgemm_nt_kernel<<<ggrid, 256>>>(nullptr, Wo, out, 3);
}